// round 14
// baseline (speedup 1.0000x reference)
#include <cuda_runtime.h>
#include <cuda_fp16.h>

#define NODES  50000
#define NEDGE  800000
#define AUGE   (NEDGE + NODES)     // 850000
#define INC    128
#define HIDC   64
#define NHEADS 4
#define H1DIM  (NHEADS * HIDC)     // 256
#define NSCAN  ((NODES + 1023) / 1024)   // 49
#define MT1    ((NODES + 127) / 128)     // 391

// ------------------------- scratch (static device memory) -------------------
__device__ __half   g_h1h  [(size_t)NODES * H1DIM];
__device__ float    g_agg1 [(size_t)NODES * H1DIM];
__device__ __half   g_h2h  [(size_t)NODES * HIDC];
__device__ float    g_agg2 [(size_t)NODES * HIDC];
__device__ __half   g_PQh  [(size_t)NODES * 2 * HIDC];
__device__ float    g_Bc   [HIDC * 2 * HIDC];
__device__ float    g_ssrc1[NODES * NHEADS];
__device__ float    g_sdst1[NODES * NHEADS];
__device__ float    g_den1 [NODES * NHEADS];
__device__ float    g_ssrc2[NODES];
__device__ float    g_sdst2[NODES];
__device__ float    g_den2 [NODES];
__device__ int      g_ei   [2 * NEDGE];
__device__ int      g_deg  [NODES];
__device__ int      g_rowp [NODES];
__device__ int      g_pos  [NODES];
__device__ int      g_bsum [NSCAN];
__device__ int      g_flag [NSCAN];
__device__ int      g_done;
__device__ int      g_srt  [AUGE];
__device__ int      g_is64;

// ------------------------- helpers ------------------------------------------
__device__ __forceinline__ float lrelu(float x) { return x >= 0.f ? x : 0.2f * x; }
__device__ __forceinline__ unsigned t32(float x) {
    unsigned r; asm("cvt.rna.tf32.f32 %0, %1;" : "=r"(r) : "f"(x)); return r;
}
__device__ __forceinline__ void mma_tf32(float4& d, const unsigned* a,
                                         unsigned b0, unsigned b1) {
    asm("mma.sync.aligned.m16n8k8.row.col.f32.tf32.tf32.f32 "
        "{%0,%1,%2,%3},{%4,%5,%6,%7},{%8,%9},{%0,%1,%2,%3};"
        : "+f"(d.x), "+f"(d.y), "+f"(d.z), "+f"(d.w)
        : "r"(a[0]), "r"(a[1]), "r"(a[2]), "r"(a[3]), "r"(b0), "r"(b1));
}

// ------------- setup + zero scores/flags + dtype detect ----------------------
__global__ void setupdet_k(const float* __restrict__ Wm1, const void* eip) {
    int i = blockIdx.x * 256 + threadIdx.x;
    if (i < NODES) {
        g_deg[i] = 1;   // self-loop
        *(float4*)(g_ssrc1 + i * 4) = make_float4(0.f, 0.f, 0.f, 0.f);
        *(float4*)(g_sdst1 + i * 4) = make_float4(0.f, 0.f, 0.f, 0.f);
        g_ssrc2[i] = 0.f;
        g_sdst2[i] = 0.f;
    }
    if (i < NSCAN) g_flag[i] = 0;
    if (i == 0)    g_done = 0;
    if (i < HIDC * 2 * HIDC) {
        int k = i >> 7, j = i & 127;
        g_Bc[i] = (j < HIDC) ? Wm1[k * HIDC + j] : Wm1[(HIDC + k) * HIDC + (j - HIDC)];
    }
    if (blockIdx.x == 0) {
        __shared__ int s;
        if (threadIdx.x == 0) s = 0;
        __syncthreads();
        const int2* q = (const int2*)eip;
        int nz = 0;
        for (int j = threadIdx.x; j < 4096; j += 256)
            if (q[j].y != 0) nz = 1;
        if (nz) s = 1;
        __syncthreads();
        if (threadIdx.x == 0) g_is64 = (s == 0) ? 1 : 0;
    }
}

// -------------------- conv + degree histogram: 2 edges/thread ----------------
__global__ void conv_k(const void* p) {
    int i = blockIdx.x * blockDim.x + threadIdx.x;   // handles elements 2i, 2i+1
    if (2 * i >= 2 * NEDGE) return;
    int v0, v1;
    if (g_is64) {
        ulonglong2 u = ((const ulonglong2*)p)[i];
        v0 = (int)u.x; v1 = (int)u.y;
    } else {
        int2 u = ((const int2*)p)[i];
        v0 = u.x; v1 = u.y;
    }
    *(int2*)(g_ei + 2 * i) = make_int2(v0, v1);
    if (2 * i >= NEDGE)     atomicAdd(&g_deg[v0], 1);
    if (2 * i + 1 >= NEDGE) atomicAdd(&g_deg[v1], 1);
}

// ---------- fused CSR scan + scatter (49 resident blocks, lookback) ----------
__global__ void __launch_bounds__(1024) scansc_k() {
    int t = threadIdx.x, b = blockIdx.x;
    int lane = t & 31, wid = t >> 5;
    int idx = b * 1024 + t;
    int v = (idx < NODES) ? g_deg[idx] : 0;

    // warp-shuffle inclusive scan
    int x = v;
    #pragma unroll
    for (int off = 1; off < 32; off <<= 1) {
        int u = __shfl_up_sync(0xffffffffu, x, off);
        if (lane >= off) x += u;
    }
    __shared__ int wsum[32];
    if (lane == 31) wsum[wid] = x;
    __syncthreads();
    if (wid == 0) {
        int y = wsum[lane];
        #pragma unroll
        for (int off = 1; off < 32; off <<= 1) {
            int u = __shfl_up_sync(0xffffffffu, y, off);
            if (lane >= off) y += u;
        }
        wsum[lane] = y;
    }
    __syncthreads();
    int incl  = x + (wid ? wsum[wid - 1] : 0);
    int total = wsum[31];

    // publish this block's aggregate
    if (t == 0) {
        g_bsum[b] = total;
        __threadfence();
        atomicExch(&g_flag[b], 1);
    }
    __syncthreads();

    // parallel lookback over predecessors
    __shared__ int sp;
    if (t == 0) sp = 0;
    __syncthreads();
    if (t < b) {
        while (atomicAdd(&g_flag[t], 0) == 0) { }
        atomicAdd(&sp, g_bsum[t]);
    }
    __syncthreads();
    int r = sp + incl - v;   // global exclusive prefix
    if (idx < NODES) { g_rowp[idx] = r; g_pos[idx] = r; }

    // quasi grid-sync (all 49 blocks resident)
    __threadfence();
    __syncthreads();
    if (t == 0) {
        atomicAdd(&g_done, 1);
        while (atomicAdd(&g_done, 0) < NSCAN) { }
    }
    __syncthreads();

    // scatter
    for (int i = b * 1024 + t; i < AUGE; i += NSCAN * 1024) {
        int s, d;
        if (i < NEDGE) { s = g_ei[i]; d = g_ei[NEDGE + i]; } else { s = d = i - NEDGE; }
        int p = atomicAdd(&g_pos[d], 1);
        g_srt[p] = s;
    }
}

// ---------------- tf32 tensor-core GEMM: 128x64 block, BK=32 ----------------
// AMODE 0: plain A; 1: relu(A/den[r,(k>>6)] + biasA[k]); 2: A/den[r] + biasA[k]
// CHALF 0: C fp32; 1: C fp16
// SH: 0 = none; else fused scores stride (4 layer1, 1 layer2)
template<int AMODE, int CHALF, int SH>
__global__ void __launch_bounds__(256) gemmt_k(
    const float* __restrict__ A, const float* __restrict__ B,
    const float* __restrict__ biasA, const float* __restrict__ den,
    void* __restrict__ Cp, int M, int K, int Nc,
    const float* __restrict__ asrc, const float* __restrict__ adst,
    float* __restrict__ ssrc, float* __restrict__ sdst)
{
    __shared__ unsigned Asm[4 * 8 * 32 * 4];
    __shared__ unsigned Bsm[2 * 4 * 2 * 32 * 4];
    int t = threadIdx.x;
    int lane = t & 31, warp = t >> 5;
    int wm = warp >> 1, wn = warp & 1;
    int m0 = blockIdx.x * 128, n0 = blockIdx.y * 64;

    float4 acc[2][4];
    #pragma unroll
    for (int i = 0; i < 2; i++)
        #pragma unroll
        for (int j = 0; j < 4; j++) acc[i][j] = make_float4(0.f, 0.f, 0.f, 0.f);

    for (int k0 = 0; k0 < K; k0 += 32) {
        #pragma unroll
        for (int i = t; i < 1024; i += 256) {
            int r = i >> 3;
            int kq = (i & 7) << 2;
            int gr = m0 + r;
            float4 v = make_float4(0.f, 0.f, 0.f, 0.f);
            if (gr < M) {
                v = *(const float4*)(A + (long)gr * K + k0 + kq);
                if (AMODE == 1) {
                    float inv = 1.f / (den[gr * 4 + ((k0 + kq) >> 6)] + 1e-16f);
                    float4 b = *(const float4*)(biasA + k0 + kq);
                    v.x = fmaxf(v.x * inv + b.x, 0.f);
                    v.y = fmaxf(v.y * inv + b.y, 0.f);
                    v.z = fmaxf(v.z * inv + b.z, 0.f);
                    v.w = fmaxf(v.w * inv + b.w, 0.f);
                } else if (AMODE == 2) {
                    float inv = 1.f / (den[gr] + 1e-16f);
                    float4 b = *(const float4*)(biasA + k0 + kq);
                    v.x = v.x * inv + b.x; v.y = v.y * inv + b.y;
                    v.z = v.z * inv + b.z; v.w = v.w * inv + b.w;
                }
            }
            int kstep = kq >> 3;
            int mtile = r >> 4, rr = r & 15;
            int j = (rr >= 8 ? 1 : 0) + ((kq & 4) ? 2 : 0);
            int lane0 = (rr & 7) << 2;
            unsigned* bp = Asm + (((kstep * 8 + mtile) * 32) + lane0) * 4 + j;
            bp[(0 ^ kstep) * 4] = t32(v.x);
            bp[(1 ^ kstep) * 4] = t32(v.y);
            bp[(2 ^ kstep) * 4] = t32(v.z);
            bp[(3 ^ kstep) * 4] = t32(v.w);
        }
        #pragma unroll
        for (int i = t; i < 512; i += 256) {
            int kk = i >> 4;
            int nq = (i & 15) << 2;
            float4 v = *(const float4*)(B + (long)(k0 + kk) * Nc + n0 + nq);
            int kstep = kk >> 3, klo = kk & 3, bsel = ((kk & 7) >= 4);
            unsigned tv[4] = { t32(v.x), t32(v.y), t32(v.z), t32(v.w) };
            #pragma unroll
            for (int c = 0; c < 4; c++) {
                int ng = nq + c;
                int g = ng >> 5, nn = ng & 31, tt = nn >> 3;
                int ln = ((nn & 7) << 2) | klo;
                Bsm[(tt >> 1) * 1024 + (((kstep * 2 + g) * 32) + ln) * 4
                    + (tt & 1) * 2 + bsel] = tv[c];
            }
        }
        __syncthreads();
        #pragma unroll
        for (int kstep = 0; kstep < 4; kstep++) {
            unsigned a[2][4], b[8];
            #pragma unroll
            for (int i = 0; i < 2; i++)
                *(uint4*)a[i] = *(const uint4*)
                    &Asm[(((kstep * 8) + (wm * 2 + i)) * 32 + (lane ^ kstep)) * 4];
            *(uint4*)&b[0] = *(const uint4*)&Bsm[(((kstep * 2 + wn) * 32) + lane) * 4];
            *(uint4*)&b[4] = *(const uint4*)&Bsm[1024 + (((kstep * 2 + wn) * 32) + lane) * 4];
            #pragma unroll
            for (int i = 0; i < 2; i++) {
                mma_tf32(acc[i][0], a[i], b[0], b[1]);
                mma_tf32(acc[i][1], a[i], b[2], b[3]);
                mma_tf32(acc[i][2], a[i], b[4], b[5]);
                mma_tf32(acc[i][3], a[i], b[6], b[7]);
            }
        }
        __syncthreads();
    }
    int mw = m0 + wm * 32;
    int nw = n0 + wn * 32;
    #pragma unroll
    for (int i = 0; i < 2; i++) {
        int rlo = mw + i * 16 + (lane >> 2);
        int rhi = rlo + 8;
        #pragma unroll
        for (int tt = 0; tt < 4; tt++) {
            int col = nw + tt * 8 + (lane & 3) * 2;
            if (CHALF) {
                __half* C = (__half*)Cp;
                if (rlo < M)
                    *(__half2*)(C + (long)rlo * Nc + col) =
                        __floats2half2_rn(acc[i][tt].x, acc[i][tt].y);
                if (rhi < M)
                    *(__half2*)(C + (long)rhi * Nc + col) =
                        __floats2half2_rn(acc[i][tt].z, acc[i][tt].w);
            } else {
                float* C = (float*)Cp;
                if (rlo < M)
                    *(float2*)(C + (long)rlo * Nc + col) = make_float2(acc[i][tt].x, acc[i][tt].y);
                if (rhi < M)
                    *(float2*)(C + (long)rhi * Nc + col) = make_float2(acc[i][tt].z, acc[i][tt].w);
            }
        }
        if (SH) {
            float sslo = 0.f, sshi = 0.f, sdlo = 0.f, sdhi = 0.f;
            #pragma unroll
            for (int tt = 0; tt < 4; tt++) {
                int col = nw + tt * 8 + (lane & 3) * 2;
                float a0v = asrc[col], a1v = asrc[col + 1];
                float d0v = adst[col], d1v = adst[col + 1];
                sslo += acc[i][tt].x * a0v + acc[i][tt].y * a1v;
                sshi += acc[i][tt].z * a0v + acc[i][tt].w * a1v;
                sdlo += acc[i][tt].x * d0v + acc[i][tt].y * d1v;
                sdhi += acc[i][tt].z * d0v + acc[i][tt].w * d1v;
            }
            #pragma unroll
            for (int off = 1; off < 4; off <<= 1) {
                sslo += __shfl_xor_sync(0xffffffffu, sslo, off);
                sshi += __shfl_xor_sync(0xffffffffu, sshi, off);
                sdlo += __shfl_xor_sync(0xffffffffu, sdlo, off);
                sdhi += __shfl_xor_sync(0xffffffffu, sdhi, off);
            }
            if ((lane & 3) == 0) {
                if (rlo < M) {
                    atomicAdd(&ssrc[rlo * SH + blockIdx.y], sslo);
                    atomicAdd(&sdst[rlo * SH + blockIdx.y], sdlo);
                }
                if (rhi < M) {
                    atomicAdd(&ssrc[rhi * SH + blockIdx.y], sshi);
                    atomicAdd(&sdst[rhi * SH + blockIdx.y], sdhi);
                }
            }
        }
    }
}

// -------- layer-1 CSR aggregation: warp per dst node, unroll-2 ---------------
__global__ void __launch_bounds__(256) eagg1c_k() {
    int node = (int)(((long)blockIdx.x * blockDim.x + threadIdx.x) >> 5);
    if (node >= NODES) return;
    int lane = threadIdx.x & 31;
    int start = g_rowp[node], deg = g_deg[node];
    float sdv = (lane < 4) ? g_sdst1[node * 4 + lane] : 0.f;
    int head = lane >> 3;
    float acc[8] = {};
    float den = 0.f;
    int e = 0;
    for (; e + 2 <= deg; e += 2) {
        int s0 = g_srt[start + e];
        int s1 = g_srt[start + e + 1];
        float ex0 = 0.f, ex1 = 0.f;
        if (lane < 4) {
            ex0 = __expf(lrelu(g_ssrc1[s0 * 4 + lane] + sdv));
            ex1 = __expf(lrelu(g_ssrc1[s1 * 4 + lane] + sdv));
            den += ex0 + ex1;
        }
        float exa = __shfl_sync(0xffffffffu, ex0, head);
        float exb = __shfl_sync(0xffffffffu, ex1, head);
        uint4 u0 = *(const uint4*)(g_h1h + (long)s0 * 256 + lane * 8);
        uint4 u1 = *(const uint4*)(g_h1h + (long)s1 * 256 + lane * 8);
        float2 a0 = __half22float2(*(__half2*)&u0.x);
        float2 a1 = __half22float2(*(__half2*)&u0.y);
        float2 a2 = __half22float2(*(__half2*)&u0.z);
        float2 a3 = __half22float2(*(__half2*)&u0.w);
        float2 b0 = __half22float2(*(__half2*)&u1.x);
        float2 b1 = __half22float2(*(__half2*)&u1.y);
        float2 b2 = __half22float2(*(__half2*)&u1.z);
        float2 b3 = __half22float2(*(__half2*)&u1.w);
        acc[0] += a0.x * exa + b0.x * exb; acc[1] += a0.y * exa + b0.y * exb;
        acc[2] += a1.x * exa + b1.x * exb; acc[3] += a1.y * exa + b1.y * exb;
        acc[4] += a2.x * exa + b2.x * exb; acc[5] += a2.y * exa + b2.y * exb;
        acc[6] += a3.x * exa + b3.x * exb; acc[7] += a3.y * exa + b3.y * exb;
    }
    if (e < deg) {
        int s0 = g_srt[start + e];
        float ex0 = 0.f;
        if (lane < 4) {
            ex0 = __expf(lrelu(g_ssrc1[s0 * 4 + lane] + sdv));
            den += ex0;
        }
        float exa = __shfl_sync(0xffffffffu, ex0, head);
        uint4 u0 = *(const uint4*)(g_h1h + (long)s0 * 256 + lane * 8);
        float2 a0 = __half22float2(*(__half2*)&u0.x);
        float2 a1 = __half22float2(*(__half2*)&u0.y);
        float2 a2 = __half22float2(*(__half2*)&u0.z);
        float2 a3 = __half22float2(*(__half2*)&u0.w);
        acc[0] += a0.x * exa; acc[1] += a0.y * exa;
        acc[2] += a1.x * exa; acc[3] += a1.y * exa;
        acc[4] += a2.x * exa; acc[5] += a2.y * exa;
        acc[6] += a3.x * exa; acc[7] += a3.y * exa;
    }
    float* ap = g_agg1 + (long)node * H1DIM + lane * 8;
    *(float4*)ap       = make_float4(acc[0], acc[1], acc[2], acc[3]);
    *(float4*)(ap + 4) = make_float4(acc[4], acc[5], acc[6], acc[7]);
    if (lane < 4) g_den1[node * 4 + lane] = den;
}

// -------- layer-2 CSR aggregation: warp per dst node, fp16 h2, unroll-2 ------
__global__ void __launch_bounds__(256) eagg2c_k() {
    int node = (int)(((long)blockIdx.x * blockDim.x + threadIdx.x) >> 5);
    if (node >= NODES) return;
    int lane = threadIdx.x & 31;
    int start = g_rowp[node], deg = g_deg[node];
    float sdv = (lane == 0) ? g_sdst2[node] : 0.f;
    float a0 = 0.f, a1 = 0.f, den = 0.f;
    int e = 0;
    for (; e + 2 <= deg; e += 2) {
        int s0 = g_srt[start + e];
        int s1 = g_srt[start + e + 1];
        float ex0 = 0.f, ex1 = 0.f;
        if (lane == 0) {
            ex0 = __expf(lrelu(g_ssrc2[s0] + sdv));
            ex1 = __expf(lrelu(g_ssrc2[s1] + sdv));
            den += ex0 + ex1;
        }
        ex0 = __shfl_sync(0xffffffffu, ex0, 0);
        ex1 = __shfl_sync(0xffffffffu, ex1, 0);
        float2 v0 = __half22float2(((const __half2*)(g_h2h + (long)s0 * HIDC))[lane]);
        float2 v1 = __half22float2(((const __half2*)(g_h2h + (long)s1 * HIDC))[lane]);
        a0 += v0.x * ex0 + v1.x * ex1;
        a1 += v0.y * ex0 + v1.y * ex1;
    }
    if (e < deg) {
        int s0 = g_srt[start + e];
        float ex0 = 0.f;
        if (lane == 0) {
            ex0 = __expf(lrelu(g_ssrc2[s0] + sdv));
            den += ex0;
        }
        ex0 = __shfl_sync(0xffffffffu, ex0, 0);
        float2 v0 = __half22float2(((const __half2*)(g_h2h + (long)s0 * HIDC))[lane]);
        a0 += v0.x * ex0;
        a1 += v0.y * ex0;
    }
    ((float2*)(g_agg2 + (long)node * HIDC))[lane] = make_float2(a0, a1);
    if (lane == 0) g_den2[node] = den;
}

// ------------------- per-edge MLP finish: 4 edges per warp -------------------
__global__ void __launch_bounds__(256) edge_k(
    const float* __restrict__ bm1, const float* __restrict__ Wm2,
    const float* __restrict__ bm2, float* __restrict__ out)
{
    long tid = (long)blockIdx.x * blockDim.x + threadIdx.x;
    int warp = (int)(tid >> 5);
    int lane = threadIdx.x & 31;
    int sub = lane >> 3;
    int l = lane & 7;
    int w = warp * 4 + sub;
    if (w >= NEDGE) return;
    int s = g_ei[w], d = g_ei[NEDGE + w];
    uint4 up = *(const uint4*)(g_PQh + (long)s * 128 + l * 8);
    uint4 uq = *(const uint4*)(g_PQh + (long)d * 128 + 64 + l * 8);
    float2 p0 = __half22float2(*(__half2*)&up.x), q0 = __half22float2(*(__half2*)&uq.x);
    float2 p1 = __half22float2(*(__half2*)&up.y), q1 = __half22float2(*(__half2*)&uq.y);
    float2 p2 = __half22float2(*(__half2*)&up.z), q2 = __half22float2(*(__half2*)&uq.z);
    float2 p3 = __half22float2(*(__half2*)&up.w), q3 = __half22float2(*(__half2*)&uq.w);
    float4 bA = *(const float4*)(bm1 + l * 8);
    float4 bB = *(const float4*)(bm1 + l * 8 + 4);
    float h0 = fmaxf(p0.x + q0.x + bA.x, 0.f);
    float h1 = fmaxf(p0.y + q0.y + bA.y, 0.f);
    float h2 = fmaxf(p1.x + q1.x + bA.z, 0.f);
    float h3 = fmaxf(p1.y + q1.y + bA.w, 0.f);
    float h4 = fmaxf(p2.x + q2.x + bB.x, 0.f);
    float h5 = fmaxf(p2.y + q2.y + bB.y, 0.f);
    float h6 = fmaxf(p3.x + q3.x + bB.z, 0.f);
    float h7 = fmaxf(p3.y + q3.y + bB.w, 0.f);
    float4 w0 = *(const float4*)(Wm2 + l * 16);
    float4 w1 = *(const float4*)(Wm2 + l * 16 + 4);
    float4 w2 = *(const float4*)(Wm2 + l * 16 + 8);
    float4 w3 = *(const float4*)(Wm2 + l * 16 + 12);
    float o0 = h0*w0.x + h1*w0.z + h2*w1.x + h3*w1.z
             + h4*w2.x + h5*w2.z + h6*w3.x + h7*w3.z;
    float o1 = h0*w0.y + h1*w0.w + h2*w1.y + h3*w1.w
             + h4*w2.y + h5*w2.w + h6*w3.y + h7*w3.w;
    #pragma unroll
    for (int off = 4; off; off >>= 1) {
        o0 += __shfl_xor_sync(0xffffffffu, o0, off);
        o1 += __shfl_xor_sync(0xffffffffu, o1, off);
    }
    if (l == 0) {
        float2 r = make_float2(o0 + bm2[0], o1 + bm2[1]);
        *(float2*)(out + (long)w * 2) = r;
    }
}

// ------------------------- launch -------------------------------------------
extern "C" void kernel_launch(void* const* d_in, const int* in_sizes, int n_in,
                              void* d_out, int out_size)
{
    const float* x   = (const float*)d_in[0];
    const void*  eir = d_in[1];
    const float* W1  = (const float*)d_in[2];
    const float* as1 = (const float*)d_in[3];
    const float* ad1 = (const float*)d_in[4];
    const float* b1  = (const float*)d_in[5];
    const float* W2  = (const float*)d_in[6];
    const float* as2 = (const float*)d_in[7];
    const float* ad2 = (const float*)d_in[8];
    const float* b2  = (const float*)d_in[9];
    const float* Wm1 = (const float*)d_in[10];
    const float* bm1 = (const float*)d_in[11];
    const float* Wm2 = (const float*)d_in[12];
    const float* bm2 = (const float*)d_in[13];
    float* out = (float*)d_out;

    void* p;
    cudaGetSymbolAddress(&p, g_h1h);   void*  h1h   = p;
    cudaGetSymbolAddress(&p, g_agg1);  float* agg1  = (float*)p;
    cudaGetSymbolAddress(&p, g_h2h);   void*  h2h   = p;
    cudaGetSymbolAddress(&p, g_agg2);  float* agg2  = (float*)p;
    cudaGetSymbolAddress(&p, g_PQh);   void*  PQh   = p;
    cudaGetSymbolAddress(&p, g_Bc);    float* Bc    = (float*)p;
    cudaGetSymbolAddress(&p, g_ssrc1); float* ssrc1 = (float*)p;
    cudaGetSymbolAddress(&p, g_sdst1); float* sdst1 = (float*)p;
    cudaGetSymbolAddress(&p, g_den1);  float* den1  = (float*)p;
    cudaGetSymbolAddress(&p, g_ssrc2); float* ssrc2 = (float*)p;
    cudaGetSymbolAddress(&p, g_sdst2); float* sdst2 = (float*)p;
    cudaGetSymbolAddress(&p, g_den2);  float* den2  = (float*)p;

    setupdet_k<<<(NODES + 255) / 256, 256>>>(Wm1, eir);
    conv_k<<<(NEDGE + 255) / 256, 256>>>(eir);     // 2 edges/thread
    scansc_k<<<NSCAN, 1024>>>();                   // fused scan + scatter

    // ---- layer 1: GEMM + fused scores (SH=4); C fp16 ----
    gemmt_k<0, 1, 4><<<dim3(MT1, H1DIM / 64), 256>>>(
        x, W1, nullptr, nullptr, h1h, NODES, INC, H1DIM, as1, ad1, ssrc1, sdst1);
    eagg1c_k<<<(NODES * 32 + 255) / 256, 256>>>();

    // ---- layer 2: GEMM + fused scores (SH=1); relu(agg1/den1+b1) A-load; C fp16
    gemmt_k<1, 1, 1><<<dim3(MT1, 1), 256>>>(
        agg1, W2, b1, den1, h2h, NODES, H1DIM, HIDC, as2, ad2, ssrc2, sdst2);
    eagg2c_k<<<(NODES * 32 + 255) / 256, 256>>>();

    // ---- edge MLP, factorized: PQ = (agg2/den2 + b2) @ [Wm1_top|Wm1_bot], fp16
    gemmt_k<2, 1, 0><<<dim3(MT1, 2), 256>>>(
        agg2, Bc, b2, den2, PQh, NODES, HIDC, 2 * HIDC,
        nullptr, nullptr, nullptr, nullptr);
    edge_k<<<(int)(((long)NEDGE / 4 * 32 + 255) / 256), 256>>>(bm1, Wm2, bm2, out);
}

// round 15
// speedup vs baseline: 1.0210x; 1.0210x over previous
#include <cuda_runtime.h>
#include <cuda_fp16.h>

#define NODES  50000
#define NEDGE  800000
#define AUGE   (NEDGE + NODES)     // 850000
#define INC    128
#define HIDC   64
#define NHEADS 4
#define H1DIM  (NHEADS * HIDC)     // 256
#define NSCAN  ((NODES + 1023) / 1024)   // 49
#define MT1    ((NODES + 127) / 128)     // 391

// ------------------------- scratch (static device memory) -------------------
__device__ __half   g_h1h  [(size_t)NODES * H1DIM];
__device__ float    g_agg1 [(size_t)NODES * H1DIM];
__device__ __half   g_h2h  [(size_t)NODES * HIDC];
__device__ float    g_agg2 [(size_t)NODES * HIDC];
__device__ __half   g_PQh  [(size_t)NODES * 2 * HIDC];
__device__ float    g_Bc   [HIDC * 2 * HIDC];
__device__ float    g_ssrc1[NODES * NHEADS];
__device__ float    g_sdst1[NODES * NHEADS];
__device__ float    g_den1 [NODES * NHEADS];
__device__ float    g_ssrc2[NODES];
__device__ float    g_sdst2[NODES];
__device__ float    g_den2 [NODES];
__device__ int      g_ei   [2 * NEDGE];
__device__ int      g_deg  [NODES];
__device__ int      g_rowp [NODES];
__device__ int      g_pos  [NODES];
__device__ int      g_bsum [NSCAN];
__device__ int      g_srt  [AUGE];
__device__ int      g_is64;

// ------------------------- helpers ------------------------------------------
__device__ __forceinline__ float lrelu(float x) { return x >= 0.f ? x : 0.2f * x; }
__device__ __forceinline__ unsigned t32(float x) {
    unsigned r; asm("cvt.rna.tf32.f32 %0, %1;" : "=r"(r) : "f"(x)); return r;
}
__device__ __forceinline__ void mma_tf32(float4& d, const unsigned* a,
                                         unsigned b0, unsigned b1) {
    asm("mma.sync.aligned.m16n8k8.row.col.f32.tf32.tf32.f32 "
        "{%0,%1,%2,%3},{%4,%5,%6,%7},{%8,%9},{%0,%1,%2,%3};"
        : "+f"(d.x), "+f"(d.y), "+f"(d.z), "+f"(d.w)
        : "r"(a[0]), "r"(a[1]), "r"(a[2]), "r"(a[3]), "r"(b0), "r"(b1));
}

// ------------- setup + zero scores + dtype detect ----------------------------
__global__ void setupdet_k(const float* __restrict__ Wm1, const void* eip) {
    int i = blockIdx.x * 256 + threadIdx.x;
    if (i < NODES) {
        g_deg[i] = 1;   // self-loop
        *(float4*)(g_ssrc1 + i * 4) = make_float4(0.f, 0.f, 0.f, 0.f);
        *(float4*)(g_sdst1 + i * 4) = make_float4(0.f, 0.f, 0.f, 0.f);
        g_ssrc2[i] = 0.f;
        g_sdst2[i] = 0.f;
    }
    if (i < HIDC * 2 * HIDC) {
        int k = i >> 7, j = i & 127;
        g_Bc[i] = (j < HIDC) ? Wm1[k * HIDC + j] : Wm1[(HIDC + k) * HIDC + (j - HIDC)];
    }
    if (blockIdx.x == 0) {
        __shared__ int s;
        if (threadIdx.x == 0) s = 0;
        __syncthreads();
        const int2* q = (const int2*)eip;
        int nz = 0;
        for (int j = threadIdx.x; j < 4096; j += 256)
            if (q[j].y != 0) nz = 1;
        if (nz) s = 1;
        __syncthreads();
        if (threadIdx.x == 0) g_is64 = (s == 0) ? 1 : 0;
    }
}

// -------------------- conv + degree histogram: 2 edges/thread ----------------
__global__ void conv_k(const void* p) {
    int i = blockIdx.x * blockDim.x + threadIdx.x;   // handles elements 2i, 2i+1
    if (2 * i >= 2 * NEDGE) return;
    int v0, v1;
    if (g_is64) {
        ulonglong2 u = ((const ulonglong2*)p)[i];
        v0 = (int)u.x; v1 = (int)u.y;
    } else {
        int2 u = ((const int2*)p)[i];
        v0 = u.x; v1 = u.y;
    }
    *(int2*)(g_ei + 2 * i) = make_int2(v0, v1);
    if (2 * i >= NEDGE)     atomicAdd(&g_deg[v0], 1);
    if (2 * i + 1 >= NEDGE) atomicAdd(&g_deg[v1], 1);
}

// ------------------------- CSR scan (2 kernels) ------------------------------
__global__ void __launch_bounds__(1024) scan1_k() {
    __shared__ int sh[1024];
    int t = threadIdx.x;
    int idx = blockIdx.x * 1024 + t;
    int v = (idx < NODES) ? g_deg[idx] : 0;
    sh[t] = v;
    __syncthreads();
    int acc = v;
    #pragma unroll
    for (int off = 1; off < 1024; off <<= 1) {
        int u = (t >= off) ? sh[t - off] : 0;
        __syncthreads();
        acc += u;
        sh[t] = acc;
        __syncthreads();
    }
    if (idx < NODES) g_rowp[idx] = acc - v;
    if (t == 1023) g_bsum[blockIdx.x] = acc;
}
__global__ void __launch_bounds__(1024) scan23_k() {
    __shared__ int off;
    if (threadIdx.x == 0) {
        int sum = 0;
        for (int j = 0; j < blockIdx.x; j++) sum += g_bsum[j];
        off = sum;
    }
    __syncthreads();
    int idx = blockIdx.x * 1024 + threadIdx.x;
    if (idx < NODES) {
        int r = g_rowp[idx] + off;
        g_rowp[idx] = r;
        g_pos[idx]  = r;
    }
}
__global__ void scatter_k() {
    int i = blockIdx.x * blockDim.x + threadIdx.x;
    if (i >= AUGE) return;
    int s, d;
    if (i < NEDGE) { s = g_ei[i]; d = g_ei[NEDGE + i]; } else { s = d = i - NEDGE; }
    int p = atomicAdd(&g_pos[d], 1);
    g_srt[p] = s;
}

// ---------------- tf32 tensor-core GEMM: 128x64 block, BK=32 ----------------
// AMODE 0: plain A; 1: relu(A/den[r,(k>>6)] + biasA[k]); 2: A/den[r] + biasA[k]
// CHALF 0: C fp32; 1: C fp16
// SH: 0 = none; else fused scores stride (4 layer1, 1 layer2)
template<int AMODE, int CHALF, int SH>
__global__ void __launch_bounds__(256) gemmt_k(
    const float* __restrict__ A, const float* __restrict__ B,
    const float* __restrict__ biasA, const float* __restrict__ den,
    void* __restrict__ Cp, int M, int K, int Nc,
    const float* __restrict__ asrc, const float* __restrict__ adst,
    float* __restrict__ ssrc, float* __restrict__ sdst)
{
    __shared__ unsigned Asm[4 * 8 * 32 * 4];
    __shared__ unsigned Bsm[2 * 4 * 2 * 32 * 4];
    int t = threadIdx.x;
    int lane = t & 31, warp = t >> 5;
    int wm = warp >> 1, wn = warp & 1;
    int m0 = blockIdx.x * 128, n0 = blockIdx.y * 64;

    float4 acc[2][4];
    #pragma unroll
    for (int i = 0; i < 2; i++)
        #pragma unroll
        for (int j = 0; j < 4; j++) acc[i][j] = make_float4(0.f, 0.f, 0.f, 0.f);

    for (int k0 = 0; k0 < K; k0 += 32) {
        #pragma unroll
        for (int i = t; i < 1024; i += 256) {
            int r = i >> 3;
            int kq = (i & 7) << 2;
            int gr = m0 + r;
            float4 v = make_float4(0.f, 0.f, 0.f, 0.f);
            if (gr < M) {
                v = *(const float4*)(A + (long)gr * K + k0 + kq);
                if (AMODE == 1) {
                    float inv = 1.f / (den[gr * 4 + ((k0 + kq) >> 6)] + 1e-16f);
                    float4 b = *(const float4*)(biasA + k0 + kq);
                    v.x = fmaxf(v.x * inv + b.x, 0.f);
                    v.y = fmaxf(v.y * inv + b.y, 0.f);
                    v.z = fmaxf(v.z * inv + b.z, 0.f);
                    v.w = fmaxf(v.w * inv + b.w, 0.f);
                } else if (AMODE == 2) {
                    float inv = 1.f / (den[gr] + 1e-16f);
                    float4 b = *(const float4*)(biasA + k0 + kq);
                    v.x = v.x * inv + b.x; v.y = v.y * inv + b.y;
                    v.z = v.z * inv + b.z; v.w = v.w * inv + b.w;
                }
            }
            int kstep = kq >> 3;
            int mtile = r >> 4, rr = r & 15;
            int j = (rr >= 8 ? 1 : 0) + ((kq & 4) ? 2 : 0);
            int lane0 = (rr & 7) << 2;
            unsigned* bp = Asm + (((kstep * 8 + mtile) * 32) + lane0) * 4 + j;
            bp[(0 ^ kstep) * 4] = t32(v.x);
            bp[(1 ^ kstep) * 4] = t32(v.y);
            bp[(2 ^ kstep) * 4] = t32(v.z);
            bp[(3 ^ kstep) * 4] = t32(v.w);
        }
        #pragma unroll
        for (int i = t; i < 512; i += 256) {
            int kk = i >> 4;
            int nq = (i & 15) << 2;
            float4 v = *(const float4*)(B + (long)(k0 + kk) * Nc + n0 + nq);
            int kstep = kk >> 3, klo = kk & 3, bsel = ((kk & 7) >= 4);
            unsigned tv[4] = { t32(v.x), t32(v.y), t32(v.z), t32(v.w) };
            #pragma unroll
            for (int c = 0; c < 4; c++) {
                int ng = nq + c;
                int g = ng >> 5, nn = ng & 31, tt = nn >> 3;
                int ln = ((nn & 7) << 2) | klo;
                Bsm[(tt >> 1) * 1024 + (((kstep * 2 + g) * 32) + ln) * 4
                    + (tt & 1) * 2 + bsel] = tv[c];
            }
        }
        __syncthreads();
        #pragma unroll
        for (int kstep = 0; kstep < 4; kstep++) {
            unsigned a[2][4], b[8];
            #pragma unroll
            for (int i = 0; i < 2; i++)
                *(uint4*)a[i] = *(const uint4*)
                    &Asm[(((kstep * 8) + (wm * 2 + i)) * 32 + (lane ^ kstep)) * 4];
            *(uint4*)&b[0] = *(const uint4*)&Bsm[(((kstep * 2 + wn) * 32) + lane) * 4];
            *(uint4*)&b[4] = *(const uint4*)&Bsm[1024 + (((kstep * 2 + wn) * 32) + lane) * 4];
            #pragma unroll
            for (int i = 0; i < 2; i++) {
                mma_tf32(acc[i][0], a[i], b[0], b[1]);
                mma_tf32(acc[i][1], a[i], b[2], b[3]);
                mma_tf32(acc[i][2], a[i], b[4], b[5]);
                mma_tf32(acc[i][3], a[i], b[6], b[7]);
            }
        }
        __syncthreads();
    }
    int mw = m0 + wm * 32;
    int nw = n0 + wn * 32;
    #pragma unroll
    for (int i = 0; i < 2; i++) {
        int rlo = mw + i * 16 + (lane >> 2);
        int rhi = rlo + 8;
        #pragma unroll
        for (int tt = 0; tt < 4; tt++) {
            int col = nw + tt * 8 + (lane & 3) * 2;
            if (CHALF) {
                __half* C = (__half*)Cp;
                if (rlo < M)
                    *(__half2*)(C + (long)rlo * Nc + col) =
                        __floats2half2_rn(acc[i][tt].x, acc[i][tt].y);
                if (rhi < M)
                    *(__half2*)(C + (long)rhi * Nc + col) =
                        __floats2half2_rn(acc[i][tt].z, acc[i][tt].w);
            } else {
                float* C = (float*)Cp;
                if (rlo < M)
                    *(float2*)(C + (long)rlo * Nc + col) = make_float2(acc[i][tt].x, acc[i][tt].y);
                if (rhi < M)
                    *(float2*)(C + (long)rhi * Nc + col) = make_float2(acc[i][tt].z, acc[i][tt].w);
            }
        }
        if (SH) {
            float sslo = 0.f, sshi = 0.f, sdlo = 0.f, sdhi = 0.f;
            #pragma unroll
            for (int tt = 0; tt < 4; tt++) {
                int col = nw + tt * 8 + (lane & 3) * 2;
                float a0v = asrc[col], a1v = asrc[col + 1];
                float d0v = adst[col], d1v = adst[col + 1];
                sslo += acc[i][tt].x * a0v + acc[i][tt].y * a1v;
                sshi += acc[i][tt].z * a0v + acc[i][tt].w * a1v;
                sdlo += acc[i][tt].x * d0v + acc[i][tt].y * d1v;
                sdhi += acc[i][tt].z * d0v + acc[i][tt].w * d1v;
            }
            #pragma unroll
            for (int off = 1; off < 4; off <<= 1) {
                sslo += __shfl_xor_sync(0xffffffffu, sslo, off);
                sshi += __shfl_xor_sync(0xffffffffu, sshi, off);
                sdlo += __shfl_xor_sync(0xffffffffu, sdlo, off);
                sdhi += __shfl_xor_sync(0xffffffffu, sdhi, off);
            }
            if ((lane & 3) == 0) {
                if (rlo < M) {
                    atomicAdd(&ssrc[rlo * SH + blockIdx.y], sslo);
                    atomicAdd(&sdst[rlo * SH + blockIdx.y], sdlo);
                }
                if (rhi < M) {
                    atomicAdd(&ssrc[rhi * SH + blockIdx.y], sshi);
                    atomicAdd(&sdst[rhi * SH + blockIdx.y], sdhi);
                }
            }
        }
    }
}

// -------- layer-1 CSR aggregation: warp per dst node, unroll-2 ---------------
__global__ void __launch_bounds__(256) eagg1c_k() {
    int node = (int)(((long)blockIdx.x * blockDim.x + threadIdx.x) >> 5);
    if (node >= NODES) return;
    int lane = threadIdx.x & 31;
    int start = g_rowp[node], deg = g_deg[node];
    float sdv = (lane < 4) ? g_sdst1[node * 4 + lane] : 0.f;
    int head = lane >> 3;
    float acc[8] = {};
    float den = 0.f;
    int e = 0;
    for (; e + 2 <= deg; e += 2) {
        int s0 = g_srt[start + e];
        int s1 = g_srt[start + e + 1];
        float ex0 = 0.f, ex1 = 0.f;
        if (lane < 4) {
            ex0 = __expf(lrelu(g_ssrc1[s0 * 4 + lane] + sdv));
            ex1 = __expf(lrelu(g_ssrc1[s1 * 4 + lane] + sdv));
            den += ex0 + ex1;
        }
        float exa = __shfl_sync(0xffffffffu, ex0, head);
        float exb = __shfl_sync(0xffffffffu, ex1, head);
        uint4 u0 = *(const uint4*)(g_h1h + (long)s0 * 256 + lane * 8);
        uint4 u1 = *(const uint4*)(g_h1h + (long)s1 * 256 + lane * 8);
        float2 a0 = __half22float2(*(__half2*)&u0.x);
        float2 a1 = __half22float2(*(__half2*)&u0.y);
        float2 a2 = __half22float2(*(__half2*)&u0.z);
        float2 a3 = __half22float2(*(__half2*)&u0.w);
        float2 b0 = __half22float2(*(__half2*)&u1.x);
        float2 b1 = __half22float2(*(__half2*)&u1.y);
        float2 b2 = __half22float2(*(__half2*)&u1.z);
        float2 b3 = __half22float2(*(__half2*)&u1.w);
        acc[0] += a0.x * exa + b0.x * exb; acc[1] += a0.y * exa + b0.y * exb;
        acc[2] += a1.x * exa + b1.x * exb; acc[3] += a1.y * exa + b1.y * exb;
        acc[4] += a2.x * exa + b2.x * exb; acc[5] += a2.y * exa + b2.y * exb;
        acc[6] += a3.x * exa + b3.x * exb; acc[7] += a3.y * exa + b3.y * exb;
    }
    if (e < deg) {
        int s0 = g_srt[start + e];
        float ex0 = 0.f;
        if (lane < 4) {
            ex0 = __expf(lrelu(g_ssrc1[s0 * 4 + lane] + sdv));
            den += ex0;
        }
        float exa = __shfl_sync(0xffffffffu, ex0, head);
        uint4 u0 = *(const uint4*)(g_h1h + (long)s0 * 256 + lane * 8);
        float2 a0 = __half22float2(*(__half2*)&u0.x);
        float2 a1 = __half22float2(*(__half2*)&u0.y);
        float2 a2 = __half22float2(*(__half2*)&u0.z);
        float2 a3 = __half22float2(*(__half2*)&u0.w);
        acc[0] += a0.x * exa; acc[1] += a0.y * exa;
        acc[2] += a1.x * exa; acc[3] += a1.y * exa;
        acc[4] += a2.x * exa; acc[5] += a2.y * exa;
        acc[6] += a3.x * exa; acc[7] += a3.y * exa;
    }
    float* ap = g_agg1 + (long)node * H1DIM + lane * 8;
    *(float4*)ap       = make_float4(acc[0], acc[1], acc[2], acc[3]);
    *(float4*)(ap + 4) = make_float4(acc[4], acc[5], acc[6], acc[7]);
    if (lane < 4) g_den1[node * 4 + lane] = den;
}

// -------- layer-2 CSR aggregation: warp per dst node, fp16 h2, unroll-2 ------
__global__ void __launch_bounds__(256) eagg2c_k() {
    int node = (int)(((long)blockIdx.x * blockDim.x + threadIdx.x) >> 5);
    if (node >= NODES) return;
    int lane = threadIdx.x & 31;
    int start = g_rowp[node], deg = g_deg[node];
    float sdv = (lane == 0) ? g_sdst2[node] : 0.f;
    float a0 = 0.f, a1 = 0.f, den = 0.f;
    int e = 0;
    for (; e + 2 <= deg; e += 2) {
        int s0 = g_srt[start + e];
        int s1 = g_srt[start + e + 1];
        float ex0 = 0.f, ex1 = 0.f;
        if (lane == 0) {
            ex0 = __expf(lrelu(g_ssrc2[s0] + sdv));
            ex1 = __expf(lrelu(g_ssrc2[s1] + sdv));
            den += ex0 + ex1;
        }
        ex0 = __shfl_sync(0xffffffffu, ex0, 0);
        ex1 = __shfl_sync(0xffffffffu, ex1, 0);
        float2 v0 = __half22float2(((const __half2*)(g_h2h + (long)s0 * HIDC))[lane]);
        float2 v1 = __half22float2(((const __half2*)(g_h2h + (long)s1 * HIDC))[lane]);
        a0 += v0.x * ex0 + v1.x * ex1;
        a1 += v0.y * ex0 + v1.y * ex1;
    }
    if (e < deg) {
        int s0 = g_srt[start + e];
        float ex0 = 0.f;
        if (lane == 0) {
            ex0 = __expf(lrelu(g_ssrc2[s0] + sdv));
            den += ex0;
        }
        ex0 = __shfl_sync(0xffffffffu, ex0, 0);
        float2 v0 = __half22float2(((const __half2*)(g_h2h + (long)s0 * HIDC))[lane]);
        a0 += v0.x * ex0;
        a1 += v0.y * ex0;
    }
    ((float2*)(g_agg2 + (long)node * HIDC))[lane] = make_float2(a0, a1);
    if (lane == 0) g_den2[node] = den;
}

// ------------------- per-edge MLP finish: 4 edges per warp -------------------
__global__ void __launch_bounds__(256) edge_k(
    const float* __restrict__ bm1, const float* __restrict__ Wm2,
    const float* __restrict__ bm2, float* __restrict__ out)
{
    long tid = (long)blockIdx.x * blockDim.x + threadIdx.x;
    int warp = (int)(tid >> 5);
    int lane = threadIdx.x & 31;
    int sub = lane >> 3;
    int l = lane & 7;
    int w = warp * 4 + sub;
    if (w >= NEDGE) return;
    int s = g_ei[w], d = g_ei[NEDGE + w];
    uint4 up = *(const uint4*)(g_PQh + (long)s * 128 + l * 8);
    uint4 uq = *(const uint4*)(g_PQh + (long)d * 128 + 64 + l * 8);
    float2 p0 = __half22float2(*(__half2*)&up.x), q0 = __half22float2(*(__half2*)&uq.x);
    float2 p1 = __half22float2(*(__half2*)&up.y), q1 = __half22float2(*(__half2*)&uq.y);
    float2 p2 = __half22float2(*(__half2*)&up.z), q2 = __half22float2(*(__half2*)&uq.z);
    float2 p3 = __half22float2(*(__half2*)&up.w), q3 = __half22float2(*(__half2*)&uq.w);
    float4 bA = *(const float4*)(bm1 + l * 8);
    float4 bB = *(const float4*)(bm1 + l * 8 + 4);
    float h0 = fmaxf(p0.x + q0.x + bA.x, 0.f);
    float h1 = fmaxf(p0.y + q0.y + bA.y, 0.f);
    float h2 = fmaxf(p1.x + q1.x + bA.z, 0.f);
    float h3 = fmaxf(p1.y + q1.y + bA.w, 0.f);
    float h4 = fmaxf(p2.x + q2.x + bB.x, 0.f);
    float h5 = fmaxf(p2.y + q2.y + bB.y, 0.f);
    float h6 = fmaxf(p3.x + q3.x + bB.z, 0.f);
    float h7 = fmaxf(p3.y + q3.y + bB.w, 0.f);
    float4 w0 = *(const float4*)(Wm2 + l * 16);
    float4 w1 = *(const float4*)(Wm2 + l * 16 + 4);
    float4 w2 = *(const float4*)(Wm2 + l * 16 + 8);
    float4 w3 = *(const float4*)(Wm2 + l * 16 + 12);
    float o0 = h0*w0.x + h1*w0.z + h2*w1.x + h3*w1.z
             + h4*w2.x + h5*w2.z + h6*w3.x + h7*w3.z;
    float o1 = h0*w0.y + h1*w0.w + h2*w1.y + h3*w1.w
             + h4*w2.y + h5*w2.w + h6*w3.y + h7*w3.w;
    #pragma unroll
    for (int off = 4; off; off >>= 1) {
        o0 += __shfl_xor_sync(0xffffffffu, o0, off);
        o1 += __shfl_xor_sync(0xffffffffu, o1, off);
    }
    if (l == 0) {
        float2 r = make_float2(o0 + bm2[0], o1 + bm2[1]);
        *(float2*)(out + (long)w * 2) = r;
    }
}

// ------------------------- launch -------------------------------------------
extern "C" void kernel_launch(void* const* d_in, const int* in_sizes, int n_in,
                              void* d_out, int out_size)
{
    const float* x   = (const float*)d_in[0];
    const void*  eir = d_in[1];
    const float* W1  = (const float*)d_in[2];
    const float* as1 = (const float*)d_in[3];
    const float* ad1 = (const float*)d_in[4];
    const float* b1  = (const float*)d_in[5];
    const float* W2  = (const float*)d_in[6];
    const float* as2 = (const float*)d_in[7];
    const float* ad2 = (const float*)d_in[8];
    const float* b2  = (const float*)d_in[9];
    const float* Wm1 = (const float*)d_in[10];
    const float* bm1 = (const float*)d_in[11];
    const float* Wm2 = (const float*)d_in[12];
    const float* bm2 = (const float*)d_in[13];
    float* out = (float*)d_out;

    void* p;
    cudaGetSymbolAddress(&p, g_h1h);   void*  h1h   = p;
    cudaGetSymbolAddress(&p, g_agg1);  float* agg1  = (float*)p;
    cudaGetSymbolAddress(&p, g_h2h);   void*  h2h   = p;
    cudaGetSymbolAddress(&p, g_agg2);  float* agg2  = (float*)p;
    cudaGetSymbolAddress(&p, g_PQh);   void*  PQh   = p;
    cudaGetSymbolAddress(&p, g_Bc);    float* Bc    = (float*)p;
    cudaGetSymbolAddress(&p, g_ssrc1); float* ssrc1 = (float*)p;
    cudaGetSymbolAddress(&p, g_sdst1); float* sdst1 = (float*)p;
    cudaGetSymbolAddress(&p, g_den1);  float* den1  = (float*)p;
    cudaGetSymbolAddress(&p, g_ssrc2); float* ssrc2 = (float*)p;
    cudaGetSymbolAddress(&p, g_sdst2); float* sdst2 = (float*)p;
    cudaGetSymbolAddress(&p, g_den2);  float* den2  = (float*)p;

    setupdet_k<<<(NODES + 255) / 256, 256>>>(Wm1, eir);
    conv_k<<<(NEDGE + 255) / 256, 256>>>(eir);     // 2 edges/thread
    scan1_k<<<NSCAN, 1024>>>();
    scan23_k<<<NSCAN, 1024>>>();
    scatter_k<<<(AUGE + 255) / 256, 256>>>();

    // ---- layer 1: GEMM + fused scores (SH=4); C fp16 ----
    gemmt_k<0, 1, 4><<<dim3(MT1, H1DIM / 64), 256>>>(
        x, W1, nullptr, nullptr, h1h, NODES, INC, H1DIM, as1, ad1, ssrc1, sdst1);
    eagg1c_k<<<(NODES * 32 + 255) / 256, 256>>>();

    // ---- layer 2: GEMM + fused scores (SH=1); relu(agg1/den1+b1) A-load; C fp16
    gemmt_k<1, 1, 1><<<dim3(MT1, 1), 256>>>(
        agg1, W2, b1, den1, h2h, NODES, H1DIM, HIDC, as2, ad2, ssrc2, sdst2);
    eagg2c_k<<<(NODES * 32 + 255) / 256, 256>>>();

    // ---- edge MLP, factorized: PQ = (agg2/den2 + b2) @ [Wm1_top|Wm1_bot], fp16
    gemmt_k<2, 1, 0><<<dim3(MT1, 2), 256>>>(
        agg2, Bc, b2, den2, PQh, NODES, HIDC, 2 * HIDC,
        nullptr, nullptr, nullptr, nullptr);
    edge_k<<<(int)(((long)NEDGE / 4 * 32 + 255) / 256), 256>>>(bm1, Wm2, bm2, out);
}